// round 4
// baseline (speedup 1.0000x reference)
#include <cuda_runtime.h>
#include <math.h>

#define TT 2048
#define HDIM 2048
#define NHEADS 32
#define NKVH 8
#define HEADD 64
#define SWIN 128
#define QKVD 3072   // HEADD * (NHEADS + 2*NKVH)

// ---------------- scratch (device globals; no allocation allowed) ----------------
__device__ float g_qkv[(size_t)TT * QKVD];
__device__ float g_nhi[TT * HDIM];            // rmsnorm output, tf32-hi
__device__ float g_nlo[TT * HDIM];            // rmsnorm output, tf32-lo
__device__ float g_ahi[TT * HDIM];            // attention output, tf32-hi
__device__ float g_alo[TT * HDIM];            // attention output, tf32-lo
__device__ float g_wqhi[(size_t)HDIM * QKVD]; // qkv weight hi
__device__ float g_wqlo[(size_t)HDIM * QKVD]; // qkv weight lo
__device__ float g_wohi[(size_t)HDIM * HDIM]; // out weight hi
__device__ float g_wolo[(size_t)HDIM * HDIM]; // out weight lo

__device__ __forceinline__ void split32(float f, float& hi, float& lo) {
    unsigned h;
    asm("cvt.rna.tf32.f32 %0, %1;" : "=r"(h) : "f"(f));
    hi = __uint_as_float(h);
    float r = f - hi;
    unsigned l;
    asm("cvt.rna.tf32.f32 %0, %1;" : "=r"(l) : "f"(r));
    lo = __uint_as_float(l);
}

// ---------------- weight split (elementwise, float4) ----------------
__global__ void splitw_kernel(const float* __restrict__ W,
                              float* __restrict__ Whi, float* __restrict__ Wlo,
                              int n4) {
    int i = blockIdx.x * 256 + threadIdx.x;
    if (i >= n4) return;
    float4 w = ((const float4*)W)[i];
    float4 h, l;
    split32(w.x, h.x, l.x); split32(w.y, h.y, l.y);
    split32(w.z, h.z, l.z); split32(w.w, h.w, l.w);
    ((float4*)Whi)[i] = h;
    ((float4*)Wlo)[i] = l;
}

// ---------------- RMSNorm (writes pre-split hi/lo) ----------------
__global__ void rmsnorm_kernel(const float* __restrict__ x,
                               const float* __restrict__ scale) {
    int t = blockIdx.x;
    const float* row = x + (size_t)t * HDIM;
    float ss = 0.f;
    for (int i = threadIdx.x; i < HDIM; i += blockDim.x) {
        float v = row[i];
        ss += v * v;
    }
    __shared__ float sh[9];
    #pragma unroll
    for (int o = 16; o; o >>= 1) ss += __shfl_xor_sync(0xffffffffu, ss, o);
    int lane = threadIdx.x & 31, wid = threadIdx.x >> 5;
    if (lane == 0) sh[wid] = ss;
    __syncthreads();
    if (threadIdx.x == 0) {
        float s = 0.f;
        for (int i = 0; i < (int)(blockDim.x >> 5); i++) s += sh[i];
        sh[8] = rsqrtf(s / (float)HDIM + 1e-5f);
    }
    __syncthreads();
    float inv = sh[8];
    for (int i = threadIdx.x; i < HDIM; i += blockDim.x) {
        float v = row[i] * inv * scale[i];
        float hi, lo;
        split32(v, hi, lo);
        g_nhi[(size_t)t * HDIM + i] = hi;
        g_nlo[(size_t)t * HDIM + i] = lo;
    }
}

// ---------------- clean TF32 tensor-core GEMM over augmented K' = 3K --------
// C[M,N] = A[M,K]@B[K,N] (3xTF32 compensated via phase pointers) + bias (+resid)
// BM=BN=128, BK=16, 256 threads, warp tile 64x32, mma.sync.m16n8k8.

#define MMA8(d, a, b) asm volatile( \
  "mma.sync.aligned.m16n8k8.row.col.f32.tf32.tf32.f32 " \
  "{%0,%1,%2,%3},{%4,%5,%6,%7},{%8,%9},{%0,%1,%2,%3};\n" \
  : "+f"((d)[0]), "+f"((d)[1]), "+f"((d)[2]), "+f"((d)[3]) \
  : "r"((a)[0]), "r"((a)[1]), "r"((a)[2]), "r"((a)[3]), \
    "r"((b)[0]), "r"((b)[1]))

__global__ __launch_bounds__(256, 1) void gemm_tf32(
    const float* __restrict__ Ahi, const float* __restrict__ Alo,
    const float* __restrict__ Bhi, const float* __restrict__ Blo,
    const float* __restrict__ bias, const float* __restrict__ resid,
    float* __restrict__ C, int N, int K)
{
    __shared__ float As[2][128][20];   // [m][k], pad 4
    __shared__ float Bs[2][16][132];   // [k][n], pad 4
    const int tid  = threadIdx.x;
    const int lane = tid & 31;
    const int wid  = tid >> 5;
    const int grp  = lane >> 2;        // 0..7
    const int qid  = lane & 3;         // 0..3
    const int wm   = (wid >> 2) * 64;  // 0 / 64
    const int wn   = (wid & 3) * 32;   // 0..96
    const int m0 = blockIdx.y * 128;
    const int n0 = blockIdx.x * 128;

    const float* Aph[3] = {Ahi, Alo, Ahi};
    const float* Bph[3] = {Bhi, Bhi, Blo};
    const int tpp = K >> 4;            // tiles per phase (=128)
    const int ntot = 3 * tpp;

    float acc[4][4][4];
    #pragma unroll
    for (int i = 0; i < 4; i++)
        #pragma unroll
        for (int j = 0; j < 4; j++)
            #pragma unroll
            for (int r = 0; r < 4; r++) acc[i][j][r] = 0.f;

    auto load_tile = [&](int buf, int t) {
        const int ph = t / tpp;
        const int k0 = (t - ph * tpp) * 16;
        const float* A = Aph[ph];
        const float* B = Bph[ph];
        #pragma unroll
        for (int i = 0; i < 2; i++) {
            int f = tid + 256 * i;
            int m = f >> 2, kq = (f & 3) << 2;
            unsigned dA = (unsigned)__cvta_generic_to_shared(&As[buf][m][kq]);
            asm volatile("cp.async.cg.shared.global [%0], [%1], 16;"
                         :: "r"(dA), "l"(A + (size_t)(m0 + m) * K + k0 + kq));
            int kb = f >> 5, nq = (f & 31) << 2;
            unsigned dB = (unsigned)__cvta_generic_to_shared(&Bs[buf][kb][nq]);
            asm volatile("cp.async.cg.shared.global [%0], [%1], 16;"
                         :: "r"(dB), "l"(B + (size_t)(k0 + kb) * N + n0 + nq));
        }
    };

    load_tile(0, 0);
    asm volatile("cp.async.commit_group;");
    for (int kt = 0; kt < ntot; kt++) {
        const int buf = kt & 1;
        if (kt + 1 < ntot) {
            load_tile(buf ^ 1, kt + 1);
            asm volatile("cp.async.commit_group;");
            asm volatile("cp.async.wait_group 1;");
        } else {
            asm volatile("cp.async.wait_group 0;");
        }
        __syncthreads();
        #pragma unroll
        for (int ks = 0; ks < 16; ks += 8) {
            unsigned b[4][2];
            #pragma unroll
            for (int nt = 0; nt < 4; nt++) {
                int cn = wn + nt * 8 + grp;
                b[nt][0] = __float_as_uint(Bs[buf][ks + qid][cn]);
                b[nt][1] = __float_as_uint(Bs[buf][ks + qid + 4][cn]);
            }
            #pragma unroll
            for (int mt = 0; mt < 4; mt++) {
                unsigned a[4];
                int rm = wm + mt * 16 + grp;
                a[0] = __float_as_uint(As[buf][rm][ks + qid]);
                a[1] = __float_as_uint(As[buf][rm + 8][ks + qid]);
                a[2] = __float_as_uint(As[buf][rm][ks + qid + 4]);
                a[3] = __float_as_uint(As[buf][rm + 8][ks + qid + 4]);
                #pragma unroll
                for (int nt = 0; nt < 4; nt++)
                    MMA8(acc[mt][nt], a, b[nt]);
            }
        }
        __syncthreads();
    }

    #pragma unroll
    for (int mt = 0; mt < 4; mt++) {
        int r0 = m0 + wm + mt * 16 + grp;
        #pragma unroll
        for (int nt = 0; nt < 4; nt++) {
            int c = n0 + wn + nt * 8 + qid * 2;
            float2 bb = *(const float2*)&bias[c];
            float2 v0 = make_float2(acc[mt][nt][0] + bb.x, acc[mt][nt][1] + bb.y);
            float2 v1 = make_float2(acc[mt][nt][2] + bb.x, acc[mt][nt][3] + bb.y);
            if (resid) {
                float2 ra = *(const float2*)&resid[(size_t)r0 * N + c];
                float2 rb = *(const float2*)&resid[(size_t)(r0 + 8) * N + c];
                v0.x += ra.x; v0.y += ra.y; v1.x += rb.x; v1.y += rb.y;
            }
            *(float2*)&C[(size_t)r0 * N + c]       = v0;
            *(float2*)&C[(size_t)(r0 + 8) * N + c] = v1;
        }
    }
}

// ---------------- RoPE (in-place on g_qkv: 32 q-heads + 8 k-heads, contiguous) ----------------
__global__ void rope_kernel(const float* __restrict__ cos_t,
                            const float* __restrict__ sin_t) {
    int t = blockIdx.x;
    const float* c = cos_t + t * 32;
    const float* s = sin_t + t * 32;
    float* rowbase = g_qkv + (size_t)t * QKVD;
    for (int i = threadIdx.x; i < 40 * 32; i += blockDim.x) {
        int head = i >> 5, r = i & 31;
        float* base = rowbase + head * HEADD;
        float x1 = base[r], x2 = base[r + 32];
        float cv = c[r], sv = s[r];
        base[r]      = x1 * cv - x2 * sv;
        base[r + 32] = x2 * cv + x1 * sv;
    }
}

// ---------------- tiled sliding-window GQA attention with sink ----------------
// grid (64 q-tiles, 8 kv heads), 512 threads; 4 GQA heads concurrent (4 warps each).
#define KMAX 160
#define KT_STRIDE 164
#define V_STRIDE 68
// float offsets in dynamic smem
#define OFF_KT 0
#define OFF_V  (64 * KT_STRIDE)                  // 10496
#define OFF_Q  (OFF_V + KMAX * V_STRIDE)         // 21376  Qs[4][32][64]
#define OFF_S  (OFF_Q + 4 * 32 * 64)             // 29568  S[16][164]
#define SMEM_FLOATS (OFF_S + 16 * KT_STRIDE)     // 32192 -> 128768 B

__global__ __launch_bounds__(512, 1) void attn3_kernel(const float* __restrict__ sinks) {
    extern __shared__ float sm[];
    float* KsT = sm + OFF_KT;   // KsT[d][k], stride KT_STRIDE
    float* Vs  = sm + OFF_V;    // Vs[k][d],  stride V_STRIDE
    float* Qs  = sm + OFF_Q;    // Qs[g][qi][d]
    float* S   = sm + OFF_S;    // S[warp][k]

    const int qt = blockIdx.x;
    const int n  = blockIdx.y;
    const int q0 = qt * 32;
    const int k0 = (q0 - SWIN > 0) ? (q0 - SWIN) : 0;
    const int kcnt = q0 + 32 - k0;      // <= 160
    const int tid = threadIdx.x;
    const int lane = tid & 31, wid = tid >> 5;

    const float* kbase = g_qkv + (size_t)k0 * QKVD + NHEADS * HEADD + n * HEADD;
    const float* vbase = kbase + NKVH * HEADD;

    // stage K (transposed) and V
    for (int f = tid; f < kcnt * 16; f += 512) {
        int r = f >> 4, dq = (f & 15) * 4;
        float4 kv = *(const float4*)(kbase + (size_t)r * QKVD + dq);
        KsT[(dq + 0) * KT_STRIDE + r] = kv.x;
        KsT[(dq + 1) * KT_STRIDE + r] = kv.y;
        KsT[(dq + 2) * KT_STRIDE + r] = kv.z;
        KsT[(dq + 3) * KT_STRIDE + r] = kv.w;
        float4 vv = *(const float4*)(vbase + (size_t)r * QKVD + dq);
        *(float4*)&Vs[r * V_STRIDE + dq] = vv;
    }
    // stage Q for all 4 heads
    for (int f = tid; f < 4 * 32 * 16; f += 512) {
        int g = f >> 9, r = (f >> 4) & 31, dq = (f & 15) * 4;
        *(float4*)&Qs[(g * 32 + r) * 64 + dq] =
            *(const float4*)(g_qkv + (size_t)(q0 + r) * QKVD + (n * 4 + g) * HEADD + dq);
    }
    __syncthreads();

    const int g  = wid & 3;             // GQA head within kv group
    const int ww = wid >> 2;            // warp within head: 0..3
    const int h  = n * 4 + g;
    const float snk = sinks[h];
    float* Sw = S + wid * KT_STRIDE;

    #pragma unroll
    for (int qq = 0; qq < 8; qq += 1) {
        // ww covers qi = ww*8 + qq?  No: 4 warps x 8 q each = 32 q.
        const int qi = ww * 8 + qq;
        const int qg = q0 + qi;
        const int khi = qg - k0;
        int klo = qg - SWIN - k0; if (klo < 0) klo = 0;
        const float* qrow = Qs + (g * 32 + qi) * 64;
        float lmax = -INFINITY;

        // pass 1: scores (4 keys per lane-iteration)
        for (int kb = lane; kb < 40; kb += 32) {
            const int kk = kb * 4;
            float s0 = 0.f, s1 = 0.f, s2 = 0.f, s3 = 0.f;
            #pragma unroll
            for (int d = 0; d < 64; d += 4) {
                float4 q4 = *(const float4*)(qrow + d);
                float4 kv;
                kv = *(const float4*)&KsT[(d + 0) * KT_STRIDE + kk];
                s0 += q4.x * kv.x; s1 += q4.x * kv.y; s2 += q4.x * kv.z; s3 += q4.x * kv.w;
                kv = *(const float4*)&KsT[(d + 1) * KT_STRIDE + kk];
                s0 += q4.y * kv.x; s1 += q4.y * kv.y; s2 += q4.y * kv.z; s3 += q4.y * kv.w;
                kv = *(const float4*)&KsT[(d + 2) * KT_STRIDE + kk];
                s0 += q4.z * kv.x; s1 += q4.z * kv.y; s2 += q4.z * kv.z; s3 += q4.z * kv.w;
                kv = *(const float4*)&KsT[(d + 3) * KT_STRIDE + kk];
                s0 += q4.w * kv.x; s1 += q4.w * kv.y; s2 += q4.w * kv.z; s3 += q4.w * kv.w;
            }
            float v0 = (kk + 0 >= klo && kk + 0 <= khi) ? s0 * 0.125f : -INFINITY;
            float v1 = (kk + 1 >= klo && kk + 1 <= khi) ? s1 * 0.125f : -INFINITY;
            float v2 = (kk + 2 >= klo && kk + 2 <= khi) ? s2 * 0.125f : -INFINITY;
            float v3 = (kk + 3 >= klo && kk + 3 <= khi) ? s3 * 0.125f : -INFINITY;
            *(float4*)&Sw[kk] = make_float4(v0, v1, v2, v3);
            lmax = fmaxf(lmax, fmaxf(fmaxf(v0, v1), fmaxf(v2, v3)));
        }
        #pragma unroll
        for (int o = 16; o; o >>= 1)
            lmax = fmaxf(lmax, __shfl_xor_sync(0xffffffffu, lmax, o));
        lmax = fmaxf(lmax, snk);

        // pass 2: exp + sum
        float lsum = 0.f;
        for (int k = lane; k < KMAX; k += 32) {
            float e = expf(Sw[k] - lmax);
            Sw[k] = e;
            lsum += e;
        }
        #pragma unroll
        for (int o = 16; o; o >>= 1)
            lsum += __shfl_xor_sync(0xffffffffu, lsum, o);
        const float inv = 1.f / (lsum + expf(snk - lmax));

        // pass 3: V accumulate (lanes over head dim)
        float a0 = 0.f, a1 = 0.f;
        const int d0 = lane, d1 = lane + 32;
        #pragma unroll 4
        for (int k = 0; k < kcnt; k++) {
            float p = Sw[k];
            a0 += p * Vs[k * V_STRIDE + d0];
            a1 += p * Vs[k * V_STRIDE + d1];
        }
        float h0, l0, h1, l1;
        split32(a0 * inv, h0, l0);
        split32(a1 * inv, h1, l1);
        size_t o0 = (size_t)qg * HDIM + h * HEADD;
        g_ahi[o0 + d0] = h0; g_alo[o0 + d0] = l0;
        g_ahi[o0 + d1] = h1; g_alo[o0 + d1] = l1;
    }
}

// ---------------- launch ----------------
extern "C" void kernel_launch(void* const* d_in, const int* in_sizes, int n_in,
                              void* d_out, int out_size) {
    const float* x          = (const float*)d_in[0];
    const float* scale      = (const float*)d_in[1];
    const float* sinks      = (const float*)d_in[2];
    const float* qkv_kernel = (const float*)d_in[3];
    const float* qkv_bias   = (const float*)d_in[4];
    const float* out_kernel = (const float*)d_in[5];
    const float* out_bias   = (const float*)d_in[6];
    const float* cos_t      = (const float*)d_in[7];
    const float* sin_t      = (const float*)d_in[8];
    // d_in[9] = mask: unused (sliding window applied structurally)
    float* out = (float*)d_out;

    void *p_qkv, *p_nhi, *p_nlo, *p_ahi, *p_alo, *p_wqhi, *p_wqlo, *p_wohi, *p_wolo;
    cudaGetSymbolAddress(&p_qkv, g_qkv);
    cudaGetSymbolAddress(&p_nhi, g_nhi);
    cudaGetSymbolAddress(&p_nlo, g_nlo);
    cudaGetSymbolAddress(&p_ahi, g_ahi);
    cudaGetSymbolAddress(&p_alo, g_alo);
    cudaGetSymbolAddress(&p_wqhi, g_wqhi);
    cudaGetSymbolAddress(&p_wqlo, g_wqlo);
    cudaGetSymbolAddress(&p_wohi, g_wohi);
    cudaGetSymbolAddress(&p_wolo, g_wolo);

    static bool attr_set = false;
    if (!attr_set) {
        cudaFuncSetAttribute(attn3_kernel,
                             cudaFuncAttributeMaxDynamicSharedMemorySize,
                             SMEM_FLOATS * 4);
        attr_set = true;
    }

    // pre-split weights (hi/lo tf32 copies)
    splitw_kernel<<<(HDIM * QKVD / 4 + 255) / 256, 256>>>(
        qkv_kernel, (float*)p_wqhi, (float*)p_wqlo, HDIM * QKVD / 4);
    splitw_kernel<<<(HDIM * HDIM / 4 + 255) / 256, 256>>>(
        out_kernel, (float*)p_wohi, (float*)p_wolo, HDIM * HDIM / 4);

    rmsnorm_kernel<<<TT, 256>>>(x, scale);

    // QKV: [2048,2048] @ [2048,3072]
    gemm_tf32<<<dim3(QKVD / 128, TT / 128), 256>>>(
        (const float*)p_nhi, (const float*)p_nlo,
        (const float*)p_wqhi, (const float*)p_wqlo,
        qkv_bias, nullptr, (float*)p_qkv, QKVD, HDIM);

    rope_kernel<<<TT, 256>>>(cos_t, sin_t);

    attn3_kernel<<<dim3(TT / 32, NKVH), 512, SMEM_FLOATS * 4>>>(sinks);

    // out-proj + residual: [2048,2048] @ [2048,2048] + x
    gemm_tf32<<<dim3(HDIM / 128, TT / 128), 256>>>(
        (const float*)p_ahi, (const float*)p_alo,
        (const float*)p_wohi, (const float*)p_wolo,
        out_bias, x, out, HDIM, HDIM);
}

// round 5
// speedup vs baseline: 2.1161x; 2.1161x over previous
#include <cuda_runtime.h>
#include <cuda_bf16.h>
#include <math.h>

#define TT 2048
#define HDIM 2048
#define NHEADS 32
#define NKVH 8
#define HEADD 64
#define SWIN 128
#define QKVD 3072   // HEADD * (NHEADS + 2*NKVH)

typedef __nv_bfloat16 bf16;

// ---------------- scratch (device globals; no allocation allowed) ----------------
__device__ float g_qkv[(size_t)TT * QKVD];
__device__ bf16 g_nhi[TT * HDIM];              // rmsnorm out, bf16 hi
__device__ bf16 g_nlo[TT * HDIM];              // rmsnorm out, bf16 lo
__device__ bf16 g_ahi[TT * HDIM];              // attention out, bf16 hi
__device__ bf16 g_alo[TT * HDIM];              // attention out, bf16 lo
__device__ bf16 g_wqhi[(size_t)HDIM * QKVD];   // qkv weight hi, transposed [N][K]
__device__ bf16 g_wqlo[(size_t)HDIM * QKVD];   // qkv weight lo, transposed [N][K]
__device__ bf16 g_wohi[(size_t)HDIM * HDIM];   // out weight hi, transposed
__device__ bf16 g_wolo[(size_t)HDIM * HDIM];   // out weight lo, transposed

__device__ __forceinline__ void splitb(float v, bf16& hi, bf16& lo) {
    hi = __float2bfloat16(v);
    lo = __float2bfloat16(v - __bfloat162float(hi));
}

// ---------------- weight split + transpose: W[K][N] fp32 -> Whi/Wlo[N][K] bf16 --
__global__ void splitw_t(const float* __restrict__ W,
                         bf16* __restrict__ Whi, bf16* __restrict__ Wlo,
                         int K, int N) {
    __shared__ float tile[32][33];
    const int kb = blockIdx.y * 32, nb = blockIdx.x * 32;
    const int tx = threadIdx.x, ty = threadIdx.y;   // 32 x 8
    #pragma unroll
    for (int i = 0; i < 32; i += 8)
        tile[ty + i][tx] = W[(size_t)(kb + ty + i) * N + nb + tx];
    __syncthreads();
    #pragma unroll
    for (int i = 0; i < 32; i += 8) {
        int n = nb + ty + i, k = kb + tx;
        float v = tile[tx][ty + i];
        bf16 h, l;
        splitb(v, h, l);
        Whi[(size_t)n * K + k] = h;
        Wlo[(size_t)n * K + k] = l;
    }
}

// ---------------- RMSNorm (writes pre-split bf16 hi/lo) ----------------
__global__ void rmsnorm_kernel(const float* __restrict__ x,
                               const float* __restrict__ scale) {
    int t = blockIdx.x;
    const float* row = x + (size_t)t * HDIM;
    float ss = 0.f;
    for (int i = threadIdx.x; i < HDIM; i += blockDim.x) {
        float v = row[i];
        ss += v * v;
    }
    __shared__ float sh[9];
    #pragma unroll
    for (int o = 16; o; o >>= 1) ss += __shfl_xor_sync(0xffffffffu, ss, o);
    int lane = threadIdx.x & 31, wid = threadIdx.x >> 5;
    if (lane == 0) sh[wid] = ss;
    __syncthreads();
    if (threadIdx.x == 0) {
        float s = 0.f;
        for (int i = 0; i < (int)(blockDim.x >> 5); i++) s += sh[i];
        sh[8] = rsqrtf(s / (float)HDIM + 1e-5f);
    }
    __syncthreads();
    float inv = sh[8];
    for (int i = threadIdx.x; i < HDIM; i += blockDim.x) {
        float v = row[i] * inv * scale[i];
        bf16 h, l;
        splitb(v, h, l);
        g_nhi[(size_t)t * HDIM + i] = h;
        g_nlo[(size_t)t * HDIM + i] = l;
    }
}

// ---------------- split-bf16 tensor-core GEMM ------------------------------
// C[M,N] = A[M,K]@B[K,N] via AhiBhi + AhiBlo + AloBhi, mma.m16n8k16.bf16.
// A stored [M][K] bf16 hi/lo; B stored transposed [N][K] bf16 hi/lo.
// BM=BN=128, BK=32, 512 threads, warp grid 4x4, warp tile 32x32.

#define MMAB(d, a, b) asm volatile( \
  "mma.sync.aligned.m16n8k16.row.col.f32.bf16.bf16.f32 " \
  "{%0,%1,%2,%3},{%4,%5,%6,%7},{%8,%9},{%0,%1,%2,%3};\n" \
  : "+f"((d)[0]), "+f"((d)[1]), "+f"((d)[2]), "+f"((d)[3]) \
  : "r"((a)[0]), "r"((a)[1]), "r"((a)[2]), "r"((a)[3]), \
    "r"((b)[0]), "r"((b)[1]))

#define SROW 40              // padded row stride in bf16 (conflict-free)
#define SA   (128 * SROW)    // 5120 bf16 per array
#define GSMEM_BYTES (2 * 4 * SA * 2)   // 2 bufs * 4 arrays * SA * 2B = 81920

extern __shared__ unsigned char dynsm[];

__global__ __launch_bounds__(512, 1) void gemm_bf16(
    const bf16* __restrict__ Ahi, const bf16* __restrict__ Alo,
    const bf16* __restrict__ Bhi, const bf16* __restrict__ Blo,
    const float* __restrict__ bias, const float* __restrict__ resid,
    float* __restrict__ C, int N, int K)
{
    bf16* sm = (bf16*)dynsm;
    const int tid  = threadIdx.x;
    const int lane = tid & 31;
    const int wid  = tid >> 5;
    const int grp  = lane >> 2;        // 0..7
    const int qid  = lane & 3;         // 0..3
    const int wm   = (wid >> 2) * 32;
    const int wn   = (wid & 3) * 32;
    const int m0 = blockIdx.y * 128;
    const int n0 = blockIdx.x * 128;

    float acc[2][4][4];
    #pragma unroll
    for (int i = 0; i < 2; i++)
        #pragma unroll
        for (int j = 0; j < 4; j++)
            #pragma unroll
            for (int r = 0; r < 4; r++) acc[i][j][r] = 0.f;

    const int row = tid >> 2;          // 0..127
    const int seg = (tid & 3) * 8;     // bf16 offset: 0,8,16,24

    auto load_tile = [&](int buf, int k0) {
        bf16* s = sm + buf * 4 * SA;
        const bf16* gah = Ahi + (size_t)(m0 + row) * K + k0 + seg;
        const bf16* gal = Alo + (size_t)(m0 + row) * K + k0 + seg;
        const bf16* gbh = Bhi + (size_t)(n0 + row) * K + k0 + seg;
        const bf16* gbl = Blo + (size_t)(n0 + row) * K + k0 + seg;
        unsigned d0 = (unsigned)__cvta_generic_to_shared(s + row * SROW + seg);
        asm volatile("cp.async.cg.shared.global [%0], [%1], 16;" :: "r"(d0), "l"(gah));
        unsigned d1 = (unsigned)__cvta_generic_to_shared(s + SA + row * SROW + seg);
        asm volatile("cp.async.cg.shared.global [%0], [%1], 16;" :: "r"(d1), "l"(gal));
        unsigned d2 = (unsigned)__cvta_generic_to_shared(s + 2 * SA + row * SROW + seg);
        asm volatile("cp.async.cg.shared.global [%0], [%1], 16;" :: "r"(d2), "l"(gbh));
        unsigned d3 = (unsigned)__cvta_generic_to_shared(s + 3 * SA + row * SROW + seg);
        asm volatile("cp.async.cg.shared.global [%0], [%1], 16;" :: "r"(d3), "l"(gbl));
    };

    load_tile(0, 0);
    asm volatile("cp.async.commit_group;");
    const int trips = K >> 5;
    for (int t = 0; t < trips; t++) {
        const int buf = t & 1;
        if (t + 1 < trips) {
            load_tile(buf ^ 1, (t + 1) << 5);
            asm volatile("cp.async.commit_group;");
            asm volatile("cp.async.wait_group 1;");
        } else {
            asm volatile("cp.async.wait_group 0;");
        }
        __syncthreads();
        bf16* s = sm + buf * 4 * SA;
        #pragma unroll
        for (int ks = 0; ks < 32; ks += 16) {
            unsigned bh[4][2], bl[4][2];
            #pragma unroll
            for (int nt = 0; nt < 4; nt++) {
                const bf16* pb = s + 2 * SA + (wn + nt * 8 + grp) * SROW + ks + 2 * qid;
                bh[nt][0] = *(const unsigned*)pb;
                bh[nt][1] = *(const unsigned*)(pb + 8);
                bl[nt][0] = *(const unsigned*)(pb + SA);
                bl[nt][1] = *(const unsigned*)(pb + SA + 8);
            }
            #pragma unroll
            for (int mt = 0; mt < 2; mt++) {
                const bf16* pa = s + (wm + mt * 16 + grp) * SROW + ks + 2 * qid;
                unsigned ah[4], al[4];
                ah[0] = *(const unsigned*)pa;
                ah[1] = *(const unsigned*)(pa + 8 * SROW);
                ah[2] = *(const unsigned*)(pa + 8);
                ah[3] = *(const unsigned*)(pa + 8 * SROW + 8);
                al[0] = *(const unsigned*)(pa + SA);
                al[1] = *(const unsigned*)(pa + SA + 8 * SROW);
                al[2] = *(const unsigned*)(pa + SA + 8);
                al[3] = *(const unsigned*)(pa + SA + 8 * SROW + 8);
                #pragma unroll
                for (int nt = 0; nt < 4; nt++) {
                    MMAB(acc[mt][nt], ah, bh[nt]);
                    MMAB(acc[mt][nt], ah, bl[nt]);
                    MMAB(acc[mt][nt], al, bh[nt]);
                }
            }
        }
        __syncthreads();
    }

    #pragma unroll
    for (int mt = 0; mt < 2; mt++) {
        int r0 = m0 + wm + mt * 16 + grp;
        #pragma unroll
        for (int nt = 0; nt < 4; nt++) {
            int c = n0 + wn + nt * 8 + qid * 2;
            float2 bb = *(const float2*)&bias[c];
            float2 v0 = make_float2(acc[mt][nt][0] + bb.x, acc[mt][nt][1] + bb.y);
            float2 v1 = make_float2(acc[mt][nt][2] + bb.x, acc[mt][nt][3] + bb.y);
            if (resid) {
                float2 ra = *(const float2*)&resid[(size_t)r0 * N + c];
                float2 rb = *(const float2*)&resid[(size_t)(r0 + 8) * N + c];
                v0.x += ra.x; v0.y += ra.y; v1.x += rb.x; v1.y += rb.y;
            }
            *(float2*)&C[(size_t)r0 * N + c]       = v0;
            *(float2*)&C[(size_t)(r0 + 8) * N + c] = v1;
        }
    }
}

// ---------------- RoPE (in-place on g_qkv) ----------------
__global__ void rope_kernel(const float* __restrict__ cos_t,
                            const float* __restrict__ sin_t) {
    int t = blockIdx.x;
    const float* c = cos_t + t * 32;
    const float* s = sin_t + t * 32;
    float* rowbase = g_qkv + (size_t)t * QKVD;
    for (int i = threadIdx.x; i < 40 * 32; i += blockDim.x) {
        int head = i >> 5, r = i & 31;
        float* base = rowbase + head * HEADD;
        float x1 = base[r], x2 = base[r + 32];
        float cv = c[r], sv = s[r];
        base[r]      = x1 * cv - x2 * sv;
        base[r + 32] = x2 * cv + x1 * sv;
    }
}

// ---------------- tiled sliding-window GQA attention with sink ----------------
// grid (64 q-tiles, 8 kv heads), 512 threads; 4 GQA heads concurrent.
#define KMAX 160
#define KT_STRIDE 164
#define V_STRIDE 68
#define OFF_KT 0
#define OFF_V  (64 * KT_STRIDE)
#define OFF_Q  (OFF_V + KMAX * V_STRIDE)
#define OFF_S  (OFF_Q + 4 * 32 * 64)
#define ATT_SMEM_FLOATS (OFF_S + 16 * KT_STRIDE)

__global__ __launch_bounds__(512, 1) void attn3_kernel(const float* __restrict__ sinks) {
    float* smf = (float*)dynsm;
    float* KsT = smf + OFF_KT;
    float* Vs  = smf + OFF_V;
    float* Qs  = smf + OFF_Q;
    float* S   = smf + OFF_S;

    const int qt = blockIdx.x;
    const int n  = blockIdx.y;
    const int q0 = qt * 32;
    const int k0 = (q0 - SWIN > 0) ? (q0 - SWIN) : 0;
    const int kcnt = q0 + 32 - k0;
    const int tid = threadIdx.x;
    const int lane = tid & 31, wid = tid >> 5;

    const float* kbase = g_qkv + (size_t)k0 * QKVD + NHEADS * HEADD + n * HEADD;
    const float* vbase = kbase + NKVH * HEADD;

    for (int f = tid; f < kcnt * 16; f += 512) {
        int r = f >> 4, dq = (f & 15) * 4;
        float4 kv = *(const float4*)(kbase + (size_t)r * QKVD + dq);
        KsT[(dq + 0) * KT_STRIDE + r] = kv.x;
        KsT[(dq + 1) * KT_STRIDE + r] = kv.y;
        KsT[(dq + 2) * KT_STRIDE + r] = kv.z;
        KsT[(dq + 3) * KT_STRIDE + r] = kv.w;
        float4 vv = *(const float4*)(vbase + (size_t)r * QKVD + dq);
        *(float4*)&Vs[r * V_STRIDE + dq] = vv;
    }
    for (int f = tid; f < 4 * 32 * 16; f += 512) {
        int g = f >> 9, r = (f >> 4) & 31, dq = (f & 15) * 4;
        *(float4*)&Qs[(g * 32 + r) * 64 + dq] =
            *(const float4*)(g_qkv + (size_t)(q0 + r) * QKVD + (n * 4 + g) * HEADD + dq);
    }
    __syncthreads();

    const int g  = wid & 3;
    const int ww = wid >> 2;
    const int h  = n * 4 + g;
    const float snk = sinks[h];
    float* Sw = S + wid * KT_STRIDE;

    #pragma unroll
    for (int qq = 0; qq < 8; qq++) {
        const int qi = ww * 8 + qq;
        const int qg = q0 + qi;
        const int khi = qg - k0;
        int klo = qg - SWIN - k0; if (klo < 0) klo = 0;
        const float* qrow = Qs + (g * 32 + qi) * 64;
        float lmax = -INFINITY;

        for (int kb = lane; kb < 40; kb += 32) {
            const int kk = kb * 4;
            float s0 = 0.f, s1 = 0.f, s2 = 0.f, s3 = 0.f;
            #pragma unroll
            for (int d = 0; d < 64; d += 4) {
                float4 q4 = *(const float4*)(qrow + d);
                float4 kv;
                kv = *(const float4*)&KsT[(d + 0) * KT_STRIDE + kk];
                s0 += q4.x * kv.x; s1 += q4.x * kv.y; s2 += q4.x * kv.z; s3 += q4.x * kv.w;
                kv = *(const float4*)&KsT[(d + 1) * KT_STRIDE + kk];
                s0 += q4.y * kv.x; s1 += q4.y * kv.y; s2 += q4.y * kv.z; s3 += q4.y * kv.w;
                kv = *(const float4*)&KsT[(d + 2) * KT_STRIDE + kk];
                s0 += q4.z * kv.x; s1 += q4.z * kv.y; s2 += q4.z * kv.z; s3 += q4.z * kv.w;
                kv = *(const float4*)&KsT[(d + 3) * KT_STRIDE + kk];
                s0 += q4.w * kv.x; s1 += q4.w * kv.y; s2 += q4.w * kv.z; s3 += q4.w * kv.w;
            }
            float v0 = (kk + 0 >= klo && kk + 0 <= khi) ? s0 * 0.125f : -INFINITY;
            float v1 = (kk + 1 >= klo && kk + 1 <= khi) ? s1 * 0.125f : -INFINITY;
            float v2 = (kk + 2 >= klo && kk + 2 <= khi) ? s2 * 0.125f : -INFINITY;
            float v3 = (kk + 3 >= klo && kk + 3 <= khi) ? s3 * 0.125f : -INFINITY;
            *(float4*)&Sw[kk] = make_float4(v0, v1, v2, v3);
            lmax = fmaxf(lmax, fmaxf(fmaxf(v0, v1), fmaxf(v2, v3)));
        }
        #pragma unroll
        for (int o = 16; o; o >>= 1)
            lmax = fmaxf(lmax, __shfl_xor_sync(0xffffffffu, lmax, o));
        lmax = fmaxf(lmax, snk);

        float lsum = 0.f;
        for (int k = lane; k < KMAX; k += 32) {
            float e = expf(Sw[k] - lmax);
            Sw[k] = e;
            lsum += e;
        }
        #pragma unroll
        for (int o = 16; o; o >>= 1)
            lsum += __shfl_xor_sync(0xffffffffu, lsum, o);
        const float inv = 1.f / (lsum + expf(snk - lmax));

        float a0 = 0.f, a1 = 0.f;
        const int d0 = lane, d1 = lane + 32;
        #pragma unroll 4
        for (int k = 0; k < kcnt; k++) {
            float p = Sw[k];
            a0 += p * Vs[k * V_STRIDE + d0];
            a1 += p * Vs[k * V_STRIDE + d1];
        }
        float r0 = a0 * inv, r1 = a1 * inv;
        bf16 h0, l0, h1, l1;
        splitb(r0, h0, l0);
        splitb(r1, h1, l1);
        size_t o0 = (size_t)qg * HDIM + h * HEADD;
        g_ahi[o0 + d0] = h0; g_alo[o0 + d0] = l0;
        g_ahi[o0 + d1] = h1; g_alo[o0 + d1] = l1;
    }
}

// ---------------- launch ----------------
extern "C" void kernel_launch(void* const* d_in, const int* in_sizes, int n_in,
                              void* d_out, int out_size) {
    const float* x          = (const float*)d_in[0];
    const float* scale      = (const float*)d_in[1];
    const float* sinks      = (const float*)d_in[2];
    const float* qkv_kernel = (const float*)d_in[3];
    const float* qkv_bias   = (const float*)d_in[4];
    const float* out_kernel = (const float*)d_in[5];
    const float* out_bias   = (const float*)d_in[6];
    const float* cos_t      = (const float*)d_in[7];
    const float* sin_t      = (const float*)d_in[8];
    // d_in[9] = mask: unused (sliding window applied structurally)
    float* out = (float*)d_out;

    void *p_qkv, *p_nhi, *p_nlo, *p_ahi, *p_alo, *p_wqhi, *p_wqlo, *p_wohi, *p_wolo;
    cudaGetSymbolAddress(&p_qkv, g_qkv);
    cudaGetSymbolAddress(&p_nhi, g_nhi);
    cudaGetSymbolAddress(&p_nlo, g_nlo);
    cudaGetSymbolAddress(&p_ahi, g_ahi);
    cudaGetSymbolAddress(&p_alo, g_alo);
    cudaGetSymbolAddress(&p_wqhi, g_wqhi);
    cudaGetSymbolAddress(&p_wqlo, g_wqlo);
    cudaGetSymbolAddress(&p_wohi, g_wohi);
    cudaGetSymbolAddress(&p_wolo, g_wolo);

    static bool attr_set = false;
    if (!attr_set) {
        cudaFuncSetAttribute(gemm_bf16,
                             cudaFuncAttributeMaxDynamicSharedMemorySize,
                             GSMEM_BYTES);
        cudaFuncSetAttribute(attn3_kernel,
                             cudaFuncAttributeMaxDynamicSharedMemorySize,
                             ATT_SMEM_FLOATS * 4);
        attr_set = true;
    }

    // pre-split + transpose weights to bf16 hi/lo, [N][K]
    splitw_t<<<dim3(QKVD / 32, HDIM / 32), dim3(32, 8)>>>(
        qkv_kernel, (bf16*)p_wqhi, (bf16*)p_wqlo, HDIM, QKVD);
    splitw_t<<<dim3(HDIM / 32, HDIM / 32), dim3(32, 8)>>>(
        out_kernel, (bf16*)p_wohi, (bf16*)p_wolo, HDIM, HDIM);

    rmsnorm_kernel<<<TT, 256>>>(x, scale);

    // QKV: [2048,2048] @ [2048,3072]
    gemm_bf16<<<dim3(QKVD / 128, TT / 128), 512, GSMEM_BYTES>>>(
        (const bf16*)p_nhi, (const bf16*)p_nlo,
        (const bf16*)p_wqhi, (const bf16*)p_wqlo,
        qkv_bias, nullptr, (float*)p_qkv, QKVD, HDIM);

    rope_kernel<<<TT, 256>>>(cos_t, sin_t);

    attn3_kernel<<<dim3(TT / 32, NKVH), 512, ATT_SMEM_FLOATS * 4>>>(sinks);

    // out-proj + residual: [2048,2048] @ [2048,2048] + x
    gemm_bf16<<<dim3(HDIM / 128, TT / 128), 512, GSMEM_BYTES>>>(
        (const bf16*)p_ahi, (const bf16*)p_alo,
        (const bf16*)p_wohi, (const bf16*)p_wolo,
        out_bias, x, out, HDIM, HDIM);
}